// round 9
// baseline (speedup 1.0000x reference)
#include <cuda_runtime.h>
#include <math.h>

// TemplatePointwiseAttention fused kernel, fp32, warp-per-8-pairs.
// Shapes: B=1, T=4, L=384, c_z=128, c_t=64, H=4, C=16.
//
// R6 (NP=8, L1 55%) + issue-count reduction: half-split float4 weight stages
// (q / o / out): lane (c=lane%16, hf=lane/16); hf splits the reduction dim,
// c owns 4 outputs; weights via LDG.128, activation bcast via LDS.128,
// cross-half combine via shfl_xor(16). Grid 760 = 5 blocks/SM (10 warps/SM).

namespace {
constexpr int L_ = 384;
constexpr int NPAIR = L_ * L_;        // 147456
constexpr int NP = 8;                 // pairs per warp iteration
constexpr int NB = NPAIR / NP;        // 18432
constexpr int WARPS = 2;
constexpr int NTHREADS = WARPS * 32;  // 64
constexpr int GRID = 152 * 5;         // 760 blocks -> 5/SM (smem 220KB/228KB)

// per-pair scratch (floats):
//   [0..271]   r_s  (4 x 68)  -> reused as u after softmax
//   [272..543] tn_s (4 x 68)  -> first 128 floats overlay zn
//   [544..607] q_s  (64)
//   [608..623] at_s (16)
//   [624..687] o_s  (64)
constexpr int SCR_P = 688;
constexpr int SCR_W = NP * SCR_P;                    // 5504 per warp
constexpr int SMEM_FLOATS = WARPS * SCR_W;           // 11008 -> 44032 B

__device__ float g_WkT[64 * 64];   // WkT[c][m] = Wk[m][c]

__device__ __forceinline__ float dot4(float4 a, float4 b) {
    return fmaf(a.x, b.x, fmaf(a.y, b.y, fmaf(a.z, b.z, a.w * b.w)));
}
__device__ __forceinline__ float4 ldcs4(const float* p) { return __ldcs((const float4*)p); }
__device__ __forceinline__ float2 ldcs2(const float* p) { return __ldcs((const float2*)p); }
} // namespace

__global__ void tpa_prep(const float* __restrict__ Wk) {
    int idx = blockIdx.x * blockDim.x + threadIdx.x;
    if (idx < 4096) {
        int m = idx >> 6, c = idx & 63;
        g_WkT[c * 64 + m] = Wk[idx];
    }
}

__global__ __launch_bounds__(NTHREADS) void tpa_fused(
    const float* __restrict__ tin,   // [4,384,384,64]
    const float* __restrict__ zin,   // [384,384,128]
    const float* __restrict__ mask,  // [4,384]
    const float* __restrict__ zg_, const float* __restrict__ zb_,
    const float* __restrict__ tg_, const float* __restrict__ tb_,
    const float* __restrict__ Wq,    // [128,64]
    const float* __restrict__ Wv,    // [64,64]
    const float* __restrict__ Wo,    // [64,128]
    const float* __restrict__ bo,    // [128]
    float* __restrict__ out)         // [384,384,128]
{
    __shared__ float sm[SMEM_FLOATS];
    const int tid  = threadIdx.x;
    const int warp = tid >> 5, lane = tid & 31;
    float* scr = sm + warp * SCR_W;

    const float4 zg = *(const float4*)(zg_ + lane * 4);
    const float4 zb = *(const float4*)(zb_ + lane * 4);
    const float2 tg = *(const float2*)(tg_ + lane * 2);
    const float2 tb = *(const float2*)(tb_ + lane * 2);

    const int c  = lane & 15;        // output-quad owner in half-split stages
    const int hf = lane >> 4;        // reduction-half owner
    const int ho = c >> 2;           // head for n = 4c..4c+3 (o-stage)
    const float4 boA = *(const float4*)(bo + 4 * c);
    const float4 boB = *(const float4*)(bo + 64 + 4 * c);

    const int idx16 = lane & 15;
    const int t_of  = idx16 >> 2;    // template idx (logits lane)
    const int h_of  = idx16 & 3;     // head idx (logits lane)

    const int gw = blockIdx.x * WARPS + warp;
    const int nw = GRID * WARPS;

    for (int b = gw; b < NB; b += nw) {
        const int p0 = b * NP;
        const int i  = p0 / L_;          // all 8 pairs share row i (8 | 384)
        const int j0 = p0 - i * L_;

        // ---- z loads + LN (8 pairs); zn overlays tn region ----
        #pragma unroll
        for (int k = 0; k < NP; k++) {
            float4 zv = ldcs4(zin + (size_t)(p0 + k) * 128 + lane * 4);
            float s  = zv.x + zv.y + zv.z + zv.w;
            float ss = zv.x * zv.x + zv.y * zv.y + zv.z * zv.z + zv.w * zv.w;
            #pragma unroll
            for (int o = 16; o > 0; o >>= 1) {
                s  += __shfl_xor_sync(0xffffffffu, s,  o);
                ss += __shfl_xor_sync(0xffffffffu, ss, o);
            }
            float mu   = s * (1.0f / 128.0f);
            float rstd = rsqrtf(fmaf(ss, 1.0f / 128.0f, -mu * mu) + 1e-5f);
            float4 znv;
            znv.x = (zv.x - mu) * rstd * zg.x + zb.x;
            znv.y = (zv.y - mu) * rstd * zg.y + zb.y;
            znv.z = (zv.z - mu) * rstd * zg.z + zb.z;
            znv.w = (zv.w - mu) * rstd * zg.w + zb.w;
            *(float4*)(scr + k * SCR_P + 272 + lane * 4) = znv;
        }
        __syncwarp();

        // ---- prefetch t batch0 (pairs 0..3, streaming) ----
        float2 tv[4][4];
        #pragma unroll
        for (int k = 0; k < 4; k++)
            #pragma unroll
            for (int t = 0; t < 4; t++)
                tv[k][t] = ldcs2(tin + ((size_t)(t * L_ + i) * L_ + (j0 + k)) * 64 + lane * 2);

        // ---- q[n] = zn . Wq[:,n] (half-split: hf owns 64 m, c owns n=4c..4c+3) ----
        {
            float4 qacc[NP];
            #pragma unroll
            for (int k = 0; k < NP; k++) qacc[k] = make_float4(0.f, 0.f, 0.f, 0.f);
            const float* wqb = Wq + (hf * 64) * 64 + 4 * c;
            #pragma unroll 2
            for (int mm = 0; mm < 64; mm += 4) {
                const float* wp = wqb + mm * 64;
                float4 w0 = *(const float4*)(wp);
                float4 w1 = *(const float4*)(wp + 64);
                float4 w2 = *(const float4*)(wp + 128);
                float4 w3 = *(const float4*)(wp + 192);
                #pragma unroll
                for (int k = 0; k < NP; k++) {
                    float4 z4 = *(const float4*)(scr + k * SCR_P + 272 + hf * 64 + mm);
                    qacc[k].x = fmaf(z4.x, w0.x, fmaf(z4.y, w1.x, fmaf(z4.z, w2.x, fmaf(z4.w, w3.x, qacc[k].x))));
                    qacc[k].y = fmaf(z4.x, w0.y, fmaf(z4.y, w1.y, fmaf(z4.z, w2.y, fmaf(z4.w, w3.y, qacc[k].y))));
                    qacc[k].z = fmaf(z4.x, w0.z, fmaf(z4.y, w1.z, fmaf(z4.z, w2.z, fmaf(z4.w, w3.z, qacc[k].z))));
                    qacc[k].w = fmaf(z4.x, w0.w, fmaf(z4.y, w1.w, fmaf(z4.z, w2.w, fmaf(z4.w, w3.w, qacc[k].w))));
                }
            }
            #pragma unroll
            for (int k = 0; k < NP; k++) {
                qacc[k].x += __shfl_xor_sync(0xffffffffu, qacc[k].x, 16);
                qacc[k].y += __shfl_xor_sync(0xffffffffu, qacc[k].y, 16);
                qacc[k].z += __shfl_xor_sync(0xffffffffu, qacc[k].z, 16);
                qacc[k].w += __shfl_xor_sync(0xffffffffu, qacc[k].w, 16);
            }
            if (hf == 0) {
                #pragma unroll
                for (int k = 0; k < NP; k++)
                    *(float4*)(scr + k * SCR_P + 544 + 4 * c) = qacc[k];
            }
        }
        __syncwarp();

        // ---- r[h][m] = sum_c q[h*16+c]*WkT[h*16+c][m]; lane owns m=2l,2l+1 ----
        #pragma unroll
        for (int h = 0; h < 4; h++) {
            float2 racc[NP];
            #pragma unroll
            for (int k = 0; k < NP; k++) racc[k] = make_float2(0.f, 0.f);
            #pragma unroll
            for (int cc = 0; cc < 16; cc += 4) {
                const float* wk = g_WkT + (h * 16 + cc) * 64 + 2 * lane;
                float2 w0 = *(const float2*)(wk);
                float2 w1 = *(const float2*)(wk + 64);
                float2 w2 = *(const float2*)(wk + 128);
                float2 w3 = *(const float2*)(wk + 192);
                #pragma unroll
                for (int k = 0; k < NP; k++) {
                    float4 qv = *(const float4*)(scr + k * SCR_P + 544 + h * 16 + cc);
                    racc[k].x = fmaf(qv.x, w0.x, fmaf(qv.y, w1.x,
                                fmaf(qv.z, w2.x, fmaf(qv.w, w3.x, racc[k].x))));
                    racc[k].y = fmaf(qv.x, w0.y, fmaf(qv.y, w1.y,
                                fmaf(qv.z, w2.y, fmaf(qv.w, w3.y, racc[k].y))));
                }
            }
            #pragma unroll
            for (int k = 0; k < NP; k++)
                *(float2*)(scr + k * SCR_P + h * 68 + 2 * lane) = racc[k];
        }
        __syncwarp();   // q/zn reads done; tn may overwrite zn region

        // ---- t layernorms, batch0 then batch1 (lane owns m = 2l, 2l+1) ----
        #pragma unroll
        for (int g = 0; g < 2; g++) {
            if (g == 1) {   // load batch1 (pairs 4..7)
                #pragma unroll
                for (int k = 0; k < 4; k++)
                    #pragma unroll
                    for (int t = 0; t < 4; t++)
                        tv[k][t] = ldcs2(tin + ((size_t)(t * L_ + i) * L_ + (j0 + 4 + k)) * 64 + lane * 2);
            }
            #pragma unroll
            for (int k = 0; k < 4; k++)
                #pragma unroll
                for (int t = 0; t < 4; t++) {
                    float2 v = tv[k][t];
                    float s  = v.x + v.y;
                    float ss = v.x * v.x + v.y * v.y;
                    #pragma unroll
                    for (int o = 16; o > 0; o >>= 1) {
                        s  += __shfl_xor_sync(0xffffffffu, s,  o);
                        ss += __shfl_xor_sync(0xffffffffu, ss, o);
                    }
                    float mu   = s * (1.0f / 64.0f);
                    float rstd = rsqrtf(fmaf(ss, 1.0f / 64.0f, -mu * mu) + 1e-5f);
                    float2 tnv;
                    tnv.x = (v.x - mu) * rstd * tg.x + tb.x;
                    tnv.y = (v.y - mu) * rstd * tg.y + tb.y;
                    *(float2*)(scr + (g * 4 + k) * SCR_P + 272 + t * 68 + lane * 2) = tnv;
                }
        }
        __syncwarp();

        // ---- logits + masked softmax over t (per pair) ----
        const float pm_i = mask[t_of * L_ + i];
        #pragma unroll
        for (int k = 0; k < NP; k++) {
            const float* tnp = scr + k * SCR_P + 272 + t_of * 68 + hf * 32;
            const float* rp  = scr + k * SCR_P + h_of * 68 + hf * 32;
            float acc = 0.f;
            #pragma unroll
            for (int s4 = 0; s4 < 32; s4 += 4)
                acc += dot4(*(const float4*)(tnp + s4), *(const float4*)(rp + s4));
            acc += __shfl_xor_sync(0xffffffffu, acc, 16);
            float logit = acc * 0.25f;

            float pm = pm_i * mask[t_of * L_ + j0 + k];
            logit = (pm == 0.0f) ? -1e9f : logit;

            float mx = fmaxf(logit, __shfl_xor_sync(0xffffffffu, logit, 4));
            mx = fmaxf(mx, __shfl_xor_sync(0xffffffffu, mx, 8));
            float e = __expf(logit - mx);
            float den = e + __shfl_xor_sync(0xffffffffu, e, 4);
            den += __shfl_xor_sync(0xffffffffu, den, 8);
            float attn = __fdividef(e, den) * pm;
            float s2 = attn + __shfl_xor_sync(0xffffffffu, attn, 4);
            s2 += __shfl_xor_sync(0xffffffffu, s2, 8);
            attn = __fdividef(attn, fmaxf(s2, 1e-8f));
            scr[k * SCR_P + 608 + t_of * 4 + h_of] = attn;  // l and l^16 same val
        }
        __syncwarp();

        // ---- u[h][m] = sum_t attn[t,h]*tn[t][m]; lane owns m=lane,lane+32 ----
        #pragma unroll
        for (int k = 0; k < NP; k++) {
            float* pk = scr + k * SCR_P;
            float u0[4] = {0.f, 0.f, 0.f, 0.f};
            float u1[4] = {0.f, 0.f, 0.f, 0.f};
            #pragma unroll
            for (int t = 0; t < 4; t++) {
                float  a0 = pk[272 + t * 68 + lane];
                float  a1 = pk[272 + t * 68 + lane + 32];
                float4 av = *(const float4*)(pk + 608 + t * 4);   // attn[t][0..3]
                u0[0] = fmaf(av.x, a0, u0[0]); u1[0] = fmaf(av.x, a1, u1[0]);
                u0[1] = fmaf(av.y, a0, u0[1]); u1[1] = fmaf(av.y, a1, u1[1]);
                u0[2] = fmaf(av.z, a0, u0[2]); u1[2] = fmaf(av.z, a1, u1[2]);
                u0[3] = fmaf(av.w, a0, u0[3]); u1[3] = fmaf(av.w, a1, u1[3]);
            }
            #pragma unroll
            for (int h = 0; h < 4; h++) {
                pk[h * 68 + lane]      = u0[h];   // overwrite r with u
                pk[h * 68 + lane + 32] = u1[h];
            }
        }
        __syncwarp();

        // ---- o[n] = u[h(n)] . Wv[:,n] (half-split: hf owns 32 m, c owns n=4c..4c+3) ----
        {
            float4 oacc[NP];
            #pragma unroll
            for (int k = 0; k < NP; k++) oacc[k] = make_float4(0.f, 0.f, 0.f, 0.f);
            const float* wvb = Wv + (hf * 32) * 64 + 4 * c;
            #pragma unroll 2
            for (int mm = 0; mm < 32; mm += 4) {
                const float* wp = wvb + mm * 64;
                float4 w0 = *(const float4*)(wp);
                float4 w1 = *(const float4*)(wp + 64);
                float4 w2 = *(const float4*)(wp + 128);
                float4 w3 = *(const float4*)(wp + 192);
                #pragma unroll
                for (int k = 0; k < NP; k++) {
                    float4 u4 = *(const float4*)(scr + k * SCR_P + ho * 68 + hf * 32 + mm);
                    oacc[k].x = fmaf(u4.x, w0.x, fmaf(u4.y, w1.x, fmaf(u4.z, w2.x, fmaf(u4.w, w3.x, oacc[k].x))));
                    oacc[k].y = fmaf(u4.x, w0.y, fmaf(u4.y, w1.y, fmaf(u4.z, w2.y, fmaf(u4.w, w3.y, oacc[k].y))));
                    oacc[k].z = fmaf(u4.x, w0.z, fmaf(u4.y, w1.z, fmaf(u4.z, w2.z, fmaf(u4.w, w3.z, oacc[k].z))));
                    oacc[k].w = fmaf(u4.x, w0.w, fmaf(u4.y, w1.w, fmaf(u4.z, w2.w, fmaf(u4.w, w3.w, oacc[k].w))));
                }
            }
            #pragma unroll
            for (int k = 0; k < NP; k++) {
                oacc[k].x += __shfl_xor_sync(0xffffffffu, oacc[k].x, 16);
                oacc[k].y += __shfl_xor_sync(0xffffffffu, oacc[k].y, 16);
                oacc[k].z += __shfl_xor_sync(0xffffffffu, oacc[k].z, 16);
                oacc[k].w += __shfl_xor_sync(0xffffffffu, oacc[k].w, 16);
            }
            if (hf == 0) {
                #pragma unroll
                for (int k = 0; k < NP; k++)
                    *(float4*)(scr + k * SCR_P + 624 + 4 * c) = oacc[k];
            }
        }
        __syncwarp();

        // ---- out[j'] = o . Wo[:,j'] + bo (half-split: hf owns 32 n,
        //      c owns j' = 4c..4c+3 and 64+4c..64+4c+3) ----
        {
            float4 accA[NP], accB[NP];
            #pragma unroll
            for (int k = 0; k < NP; k++) {
                accA[k] = make_float4(0.f, 0.f, 0.f, 0.f);
                accB[k] = make_float4(0.f, 0.f, 0.f, 0.f);
            }
            const float* wob = Wo + (hf * 32) * 128 + 4 * c;
            #pragma unroll 2
            for (int nn = 0; nn < 32; nn += 2) {
                const float* wp = wob + nn * 128;
                float4 wA0 = *(const float4*)(wp);
                float4 wB0 = *(const float4*)(wp + 64);
                float4 wA1 = *(const float4*)(wp + 128);
                float4 wB1 = *(const float4*)(wp + 192);
                #pragma unroll
                for (int k = 0; k < NP; k++) {
                    float2 o2 = *(const float2*)(scr + k * SCR_P + 624 + hf * 32 + nn);
                    accA[k].x = fmaf(o2.x, wA0.x, fmaf(o2.y, wA1.x, accA[k].x));
                    accA[k].y = fmaf(o2.x, wA0.y, fmaf(o2.y, wA1.y, accA[k].y));
                    accA[k].z = fmaf(o2.x, wA0.z, fmaf(o2.y, wA1.z, accA[k].z));
                    accA[k].w = fmaf(o2.x, wA0.w, fmaf(o2.y, wA1.w, accA[k].w));
                    accB[k].x = fmaf(o2.x, wB0.x, fmaf(o2.y, wB1.x, accB[k].x));
                    accB[k].y = fmaf(o2.x, wB0.y, fmaf(o2.y, wB1.y, accB[k].y));
                    accB[k].z = fmaf(o2.x, wB0.z, fmaf(o2.y, wB1.z, accB[k].z));
                    accB[k].w = fmaf(o2.x, wB0.w, fmaf(o2.y, wB1.w, accB[k].w));
                }
            }
            #pragma unroll
            for (int k = 0; k < NP; k++) {
                accA[k].x += __shfl_xor_sync(0xffffffffu, accA[k].x, 16);
                accA[k].y += __shfl_xor_sync(0xffffffffu, accA[k].y, 16);
                accA[k].z += __shfl_xor_sync(0xffffffffu, accA[k].z, 16);
                accA[k].w += __shfl_xor_sync(0xffffffffu, accA[k].w, 16);
                accB[k].x += __shfl_xor_sync(0xffffffffu, accB[k].x, 16);
                accB[k].y += __shfl_xor_sync(0xffffffffu, accB[k].y, 16);
                accB[k].z += __shfl_xor_sync(0xffffffffu, accB[k].z, 16);
                accB[k].w += __shfl_xor_sync(0xffffffffu, accB[k].w, 16);
            }
            if (hf == 0) {
                #pragma unroll
                for (int k = 0; k < NP; k++) {
                    float4 ra, rb;
                    ra.x = accA[k].x + boA.x; ra.y = accA[k].y + boA.y;
                    ra.z = accA[k].z + boA.z; ra.w = accA[k].w + boA.w;
                    rb.x = accB[k].x + boB.x; rb.y = accB[k].y + boB.y;
                    rb.z = accB[k].z + boB.z; rb.w = accB[k].w + boB.w;
                    __stcs((float4*)(out + (size_t)(p0 + k) * 128 + 4 * c), ra);
                    __stcs((float4*)(out + (size_t)(p0 + k) * 128 + 64 + 4 * c), rb);
                }
            }
        }
        __syncwarp();   // scratch reuse barrier before next block
    }
}

extern "C" void kernel_launch(void* const* d_in, const int* in_sizes, int n_in,
                              void* d_out, int out_size) {
    (void)in_sizes; (void)n_in; (void)out_size;
    tpa_prep<<<16, 256>>>((const float*)d_in[8]);   // Wk
    tpa_fused<<<GRID, NTHREADS>>>(
        (const float*)d_in[0],  // t
        (const float*)d_in[1],  // z
        (const float*)d_in[2],  // template_mask
        (const float*)d_in[3],  // z_ln_g
        (const float*)d_in[4],  // z_ln_b
        (const float*)d_in[5],  // t_ln_g
        (const float*)d_in[6],  // t_ln_b
        (const float*)d_in[7],  // Wq
        (const float*)d_in[9],  // Wv
        (const float*)d_in[10], // Wo
        (const float*)d_in[11], // bo
        (float*)d_out);
}